// round 12
// baseline (speedup 1.0000x reference)
#include <cuda_runtime.h>
#include <math_constants.h>

#define HH 512
#define WW 1024
#define NPIX (HH * WW)      // 524288 = 2^19
#define KNB 15
#define GAMMA_F 0.1f

#define P2_BLOCK 256
#define P2_GRID  (NPIX / P2_BLOCK)   // 2048
#define TILE 5
#define NTILE (KNB / TILE)            // 3

// Packed per-pixel data, 16 bytes: (s, nx, ny, nz).
__device__ float4 g_packed[NPIX];
__device__ float  g_partials[P2_GRID];

// Direction from pixel index (ERP grid), fast intrinsics.
__device__ __forceinline__ void erp_dir(int i, float& dx, float& dy, float& dz) {
    int row = i >> 10;          // W = 1024
    int col = i & 1023;
    float lat = 0.5f * CUDART_PI_F - (row + 0.5f) * (CUDART_PI_F / HH);
    float lon = (col + 0.5f) * (2.0f * CUDART_PI_F / WW) - CUDART_PI_F;
    float sla = __sinf(lat), cla = __cosf(lat);
    float slo = __sinf(lon), clo = __cosf(lon);
    dx = cla * slo;
    dy = sla;
    dz = cla * clo;
}

// ---------------- Pass 1: interleave {s, nx, ny, nz}, x4 unrolled ----------------
__global__ void __launch_bounds__(256) pack_kernel(const float* __restrict__ sig1,
                                                   const float* __restrict__ sig2) {
    int base = blockIdx.x * 1024 + threadIdx.x;   // 512 blocks, 4 pixels/thread
    float s0[4], nx0[4], ny0[4], nz0[4];
#pragma unroll
    for (int q = 0; q < 4; q++) {
        int i = base + q * 256;
        s0[q]  = sig1[i];
        nx0[q] = sig2[i];
        ny0[q] = sig2[NPIX + i];
        nz0[q] = sig2[2 * NPIX + i];
    }
#pragma unroll
    for (int q = 0; q < 4; q++) {
        int i = base + q * 256;
        g_packed[i] = make_float4(s0[q], nx0[q], ny0[q], nz0[q]);
    }
    // Signal dependent grid may launch (memory visibility is still gated by
    // the dependent's griddepcontrol.wait, which waits for full completion).
    asm volatile("griddepcontrol.launch_dependents;");
}

// ---------------- Pass 2: per-pixel loss (R5 shape) with PDL prologue ----------------
// Launched with programmatic stream serialization: starts while pack_kernel is
// still running, streams all 15 neighbour indices (independent of g_packed),
// then griddepcontrol.wait gates the first g_packed access.
__global__ void __launch_bounds__(P2_BLOCK) loss_kernel(const float* __restrict__ weights,
                                                        const int* __restrict__ nb) {
    int i = blockIdx.x * P2_BLOCK + threadIdx.x;

    // PDL prologue: all neighbour indices (reads only harness input 'nb')
    int idx[KNB];
#pragma unroll
    for (int k = 0; k < KNB; k++)
        idx[k] = __ldcs(&nb[k * NPIX + i]) & (NPIX - 1);

    // Wait for pack_kernel completion (all g_packed stores visible after this)
    asm volatile("griddepcontrol.wait;" ::: "memory");

    // Own pixel (coalesced 16B load + analytic direction)
    float4 E = g_packed[i];
    float dix, diy, diz;
    erp_dir(i, dix, diy, diz);
    float nix = E.y, niy = E.z, niz = E.w;
    float pn_i = E.x * (dix * nix + diy * niy + diz * niz);

    float acc1 = 0.0f;   // sum_k (aux1*w)^2
    float acc2 = 0.0f;   // sum_k aux2*w

#pragma unroll
    for (int t = 0; t < NTILE; t++) {
        // Phase A: 5 gathers in flight simultaneously (one LDG.128 each)
        float4 e[TILE];
#pragma unroll
        for (int u = 0; u < TILE; u++)
            e[u] = __ldg(&g_packed[idx[t * TILE + u]]);

        // Phase B: weights for this tile (coalesced, evict-first)
        float wv[TILE];
#pragma unroll
        for (int u = 0; u < TILE; u++)
            wv[u] = __ldcs(&weights[(t * TILE + u) * NPIX + i]);

        // Phase C: math
#pragma unroll
        for (int u = 0; u < TILE; u++) {
            float djx, djy, djz;
            erp_dir(idx[t * TILE + u], djx, djy, djz);

            float dotpn = e[u].x * (djx * nix + djy * niy + djz * niz);
            float aux1 = pn_i - dotpn;

            float ddx = nix - e[u].y;
            float ddy = niy - e[u].z;
            float ddz = niz - e[u].w;
            float aux2 = sqrtf(ddx * ddx + ddy * ddy + ddz * ddz);

            float tt = aux1 * wv[u];
            acc1 += tt * tt;
            acc2 += aux2 * wv[u];
        }
    }

    float v = sqrtf(acc1) + GAMMA_F * acc2;

    // Deterministic block tree-reduce
    __shared__ float sm[P2_BLOCK];
    sm[threadIdx.x] = v;
    __syncthreads();
#pragma unroll
    for (int s = P2_BLOCK / 2; s > 0; s >>= 1) {
        if (threadIdx.x < s) sm[threadIdx.x] += sm[threadIdx.x + s];
        __syncthreads();
    }
    if (threadIdx.x == 0) g_partials[blockIdx.x] = sm[0];
}

// ---------------- Pass 3: deterministic final reduce ----------------
__global__ void __launch_bounds__(1024) finalize_kernel(float* __restrict__ out) {
    __shared__ float sm[1024];
    float v = 0.0f;
#pragma unroll
    for (int idx = threadIdx.x; idx < P2_GRID; idx += 1024)
        v += g_partials[idx];
    sm[threadIdx.x] = v;
    __syncthreads();
#pragma unroll
    for (int s = 512; s > 0; s >>= 1) {
        if (threadIdx.x < s) sm[threadIdx.x] += sm[threadIdx.x + s];
        __syncthreads();
    }
    if (threadIdx.x == 0)
        out[0] = sm[0] * (1.0f / (float)NPIX);   // MULTIPLIER = 1.0
}

extern "C" void kernel_launch(void* const* d_in, const int* in_sizes, int n_in,
                              void* d_out, int out_size) {
    const float* sig1    = (const float*)d_in[0];   // N f32
    const float* sig2    = (const float*)d_in[1];   // 3N f32
    const float* weights = (const float*)d_in[2];   // K*N f32
    const int*   nb      = (const int*)d_in[3];     // K*N int32
    float* out = (float*)d_out;

    pack_kernel<<<NPIX / 1024, 256>>>(sig1, sig2);

    // Loss kernel with programmatic dependent launch: overlaps its index
    // streaming with pack_kernel's tail.
    cudaLaunchConfig_t cfg = {};
    cfg.gridDim  = dim3(P2_GRID, 1, 1);
    cfg.blockDim = dim3(P2_BLOCK, 1, 1);
    cfg.dynamicSmemBytes = 0;
    cudaLaunchAttribute attrs[1];
    attrs[0].id = cudaLaunchAttributeProgrammaticStreamSerialization;
    attrs[0].val.programmaticStreamSerializationAllowed = 1;
    cfg.attrs = attrs;
    cfg.numAttrs = 1;
    cudaLaunchKernelEx(&cfg, loss_kernel, weights, nb);

    finalize_kernel<<<1, 1024>>>(out);
}

// round 13
// speedup vs baseline: 1.4305x; 1.4305x over previous
#include <cuda_runtime.h>
#include <math_constants.h>

#define HH 512
#define WW 1024
#define NPIX (HH * WW)      // 524288 = 2^19
#define KNB 15
#define GAMMA_F 0.1f

#define P2_BLOCK 256
#define P2_GRID  (NPIX / P2_BLOCK)   // 2048
#define TILE 5
#define NTILE (KNB / TILE)            // 3

// Packed per-pixel data, 16 bytes: (s, nx, ny, nz).
__device__ float4 g_packed[NPIX];
__device__ float  g_partials[P2_GRID];

// Direction from pixel index (ERP grid), fast intrinsics.
__device__ __forceinline__ void erp_dir(int i, float& dx, float& dy, float& dz) {
    int row = i >> 10;          // W = 1024
    int col = i & 1023;
    float lat = 0.5f * CUDART_PI_F - (row + 0.5f) * (CUDART_PI_F / HH);
    float lon = (col + 0.5f) * (2.0f * CUDART_PI_F / WW) - CUDART_PI_F;
    float sla = __sinf(lat), cla = __cosf(lat);
    float slo = __sinf(lon), clo = __cosf(lon);
    dx = cla * slo;
    dy = sla;
    dz = cla * clo;
}

// ---------------- Pass 1: interleave {s, nx, ny, nz}, fully vectorized ----------------
// Each thread: 4 consecutive pixels = 4x LDG.128 in + 4x STG.128 out.
__global__ void __launch_bounds__(256) pack_kernel(const float4* __restrict__ sig1v,
                                                   const float4* __restrict__ sig2v) {
    int p = blockIdx.x * 256 + threadIdx.x;      // 131072 threads, 4 px each

    float4 s4  = sig1v[p];
    float4 nx4 = sig2v[p];
    float4 ny4 = sig2v[(NPIX / 4) + p];
    float4 nz4 = sig2v[2 * (NPIX / 4) + p];

    int base = p * 4;
    g_packed[base + 0] = make_float4(s4.x, nx4.x, ny4.x, nz4.x);
    g_packed[base + 1] = make_float4(s4.y, nx4.y, ny4.y, nz4.y);
    g_packed[base + 2] = make_float4(s4.z, nx4.z, ny4.z, nz4.z);
    g_packed[base + 3] = make_float4(s4.w, nx4.w, ny4.w, nz4.w);
}

// ---------------- Pass 2: per-pixel loss (R5 proven-best shape) ----------------
__global__ void __launch_bounds__(P2_BLOCK) loss_kernel(const float* __restrict__ weights,
                                                        const int* __restrict__ nb) {
    int i = blockIdx.x * P2_BLOCK + threadIdx.x;

    // All neighbour indices (independent coalesced loads, issue back-to-back)
    int idx[KNB];
#pragma unroll
    for (int k = 0; k < KNB; k++)
        idx[k] = __ldcs(&nb[k * NPIX + i]) & (NPIX - 1);

    // Own pixel (coalesced 16B load + analytic direction)
    float4 E = g_packed[i];
    float dix, diy, diz;
    erp_dir(i, dix, diy, diz);
    float nix = E.y, niy = E.z, niz = E.w;
    float pn_i = E.x * (dix * nix + diy * niy + diz * niz);

    float acc1 = 0.0f;   // sum_k (aux1*w)^2
    float acc2 = 0.0f;   // sum_k aux2*w

#pragma unroll
    for (int t = 0; t < NTILE; t++) {
        // Phase A: 5 gathers in flight simultaneously (one LDG.128 each)
        float4 e[TILE];
#pragma unroll
        for (int u = 0; u < TILE; u++)
            e[u] = __ldg(&g_packed[idx[t * TILE + u]]);

        // Phase B: weights for this tile (coalesced, evict-first)
        float wv[TILE];
#pragma unroll
        for (int u = 0; u < TILE; u++)
            wv[u] = __ldcs(&weights[(t * TILE + u) * NPIX + i]);

        // Phase C: math
#pragma unroll
        for (int u = 0; u < TILE; u++) {
            float djx, djy, djz;
            erp_dir(idx[t * TILE + u], djx, djy, djz);

            float dotpn = e[u].x * (djx * nix + djy * niy + djz * niz);
            float aux1 = pn_i - dotpn;

            float ddx = nix - e[u].y;
            float ddy = niy - e[u].z;
            float ddz = niz - e[u].w;
            float aux2 = sqrtf(ddx * ddx + ddy * ddy + ddz * ddz);

            float tt = aux1 * wv[u];
            acc1 += tt * tt;
            acc2 += aux2 * wv[u];
        }
    }

    float v = sqrtf(acc1) + GAMMA_F * acc2;

    // Deterministic block tree-reduce
    __shared__ float sm[P2_BLOCK];
    sm[threadIdx.x] = v;
    __syncthreads();
#pragma unroll
    for (int s = P2_BLOCK / 2; s > 0; s >>= 1) {
        if (threadIdx.x < s) sm[threadIdx.x] += sm[threadIdx.x + s];
        __syncthreads();
    }
    if (threadIdx.x == 0) g_partials[blockIdx.x] = sm[0];
}

// ---------------- Pass 3: deterministic final reduce ----------------
__global__ void __launch_bounds__(1024) finalize_kernel(float* __restrict__ out) {
    __shared__ float sm[1024];
    float v = 0.0f;
#pragma unroll
    for (int idx = threadIdx.x; idx < P2_GRID; idx += 1024)
        v += g_partials[idx];
    sm[threadIdx.x] = v;
    __syncthreads();
#pragma unroll
    for (int s = 512; s > 0; s >>= 1) {
        if (threadIdx.x < s) sm[threadIdx.x] += sm[threadIdx.x + s];
        __syncthreads();
    }
    if (threadIdx.x == 0)
        out[0] = sm[0] * (1.0f / (float)NPIX);   // MULTIPLIER = 1.0
}

extern "C" void kernel_launch(void* const* d_in, const int* in_sizes, int n_in,
                              void* d_out, int out_size) {
    const float4* sig1v  = (const float4*)d_in[0];  // N f32 (16B-aligned)
    const float4* sig2v  = (const float4*)d_in[1];  // 3N f32 (16B-aligned)
    const float* weights = (const float*)d_in[2];   // K*N f32
    const int*   nb      = (const int*)d_in[3];     // K*N int32
    float* out = (float*)d_out;

    pack_kernel<<<NPIX / 1024, 256>>>(sig1v, sig2v);
    loss_kernel<<<P2_GRID, P2_BLOCK>>>(weights, nb);
    finalize_kernel<<<1, 1024>>>(out);
}

// round 14
// speedup vs baseline: 1.5000x; 1.0486x over previous
#include <cuda_runtime.h>
#include <math_constants.h>

#define HH 512
#define WW 1024
#define NPIX (HH * WW)      // 524288 = 2^19
#define KNB 15
#define GAMMA_F 0.1f

#define P2_BLOCK 256
#define P2_GRID  (NPIX / P2_BLOCK)   // 2048
#define TILE 5
#define NTILE (KNB / TILE)            // 3

// Packed per-pixel data, 16 bytes: (s, nx, ny, nz).
__device__ float4 g_packed[NPIX];
__device__ float  g_partials[P2_GRID];
__device__ unsigned int g_done_ctr;

// Direction from pixel index (ERP grid), fast intrinsics.
__device__ __forceinline__ void erp_dir(int i, float& dx, float& dy, float& dz) {
    int row = i >> 10;          // W = 1024
    int col = i & 1023;
    float lat = 0.5f * CUDART_PI_F - (row + 0.5f) * (CUDART_PI_F / HH);
    float lon = (col + 0.5f) * (2.0f * CUDART_PI_F / WW) - CUDART_PI_F;
    float sla = __sinf(lat), cla = __cosf(lat);
    float slo = __sinf(lon), clo = __cosf(lon);
    dx = cla * slo;
    dy = sla;
    dz = cla * clo;
}

// ---------------- Pass 1: interleave {s, nx, ny, nz}, 1 px/thread, 2048 blocks ----------------
__global__ void __launch_bounds__(256) pack_kernel(const float* __restrict__ sig1,
                                                   const float* __restrict__ sig2) {
    if (blockIdx.x == 0 && threadIdx.x == 0) g_done_ctr = 0;

    int i = blockIdx.x * 256 + threadIdx.x;
    float s  = __ldcs(&sig1[i]);                 // single-use streams: evict-first
    float nx = __ldcs(&sig2[i]);
    float ny = __ldcs(&sig2[NPIX + i]);
    float nz = __ldcs(&sig2[2 * NPIX + i]);
    g_packed[i] = make_float4(s, nx, ny, nz);
}

// ---------------- Pass 2: per-pixel loss + fused final reduce (R5 champion shape) ----------------
__global__ void __launch_bounds__(P2_BLOCK) loss_kernel(const float* __restrict__ weights,
                                                        const int* __restrict__ nb,
                                                        float* __restrict__ out) {
    int i = blockIdx.x * P2_BLOCK + threadIdx.x;

    // Preload ALL 15 neighbour indices: maximum early MLP, addresses become
    // pure register reads for the gather tiles.
    int idx[KNB];
#pragma unroll
    for (int k = 0; k < KNB; k++)
        idx[k] = __ldcs(&nb[k * NPIX + i]) & (NPIX - 1);

    // Own pixel (coalesced 16B load + analytic direction)
    float4 E = g_packed[i];
    float dix, diy, diz;
    erp_dir(i, dix, diy, diz);
    float nix = E.y, niy = E.z, niz = E.w;
    float pn_i = E.x * (dix * nix + diy * niy + diz * niz);

    float acc1 = 0.0f;   // sum_k (aux1*w)^2
    float acc2 = 0.0f;   // sum_k aux2*w

#pragma unroll
    for (int t = 0; t < NTILE; t++) {
        // Phase A: 5 gathers in flight simultaneously (one LDG.128 each)
        float4 e[TILE];
#pragma unroll
        for (int u = 0; u < TILE; u++)
            e[u] = __ldg(&g_packed[idx[t * TILE + u]]);

        // Phase B: weights for this tile (coalesced, evict-first)
        float wv[TILE];
#pragma unroll
        for (int u = 0; u < TILE; u++)
            wv[u] = __ldcs(&weights[(t * TILE + u) * NPIX + i]);

        // Phase C: math
#pragma unroll
        for (int u = 0; u < TILE; u++) {
            float djx, djy, djz;
            erp_dir(idx[t * TILE + u], djx, djy, djz);

            float dotpn = e[u].x * (djx * nix + djy * niy + djz * niz);
            float aux1 = pn_i - dotpn;

            float ddx = nix - e[u].y;
            float ddy = niy - e[u].z;
            float ddz = niz - e[u].w;
            float aux2 = sqrtf(ddx * ddx + ddy * ddy + ddz * ddz);

            float tt = aux1 * wv[u];
            acc1 += tt * tt;
            acc2 += aux2 * wv[u];
        }
    }

    float v = sqrtf(acc1) + GAMMA_F * acc2;

    // Deterministic block tree-reduce
    __shared__ float sm[P2_BLOCK];
    sm[threadIdx.x] = v;
    __syncthreads();
#pragma unroll
    for (int s = P2_BLOCK / 2; s > 0; s >>= 1) {
        if (threadIdx.x < s) sm[threadIdx.x] += sm[threadIdx.x + s];
        __syncthreads();
    }

    __shared__ bool amLast;
    if (threadIdx.x == 0) {
        g_partials[blockIdx.x] = sm[0];
        __threadfence();
        unsigned int prev = atomicAdd(&g_done_ctr, 1u);
        amLast = (prev == P2_GRID - 1);
    }
    __syncthreads();

    // Last block: fixed-order tree reduce over all partials (bit-deterministic)
    if (amLast) {
        float acc = 0.0f;
#pragma unroll
        for (int p = threadIdx.x; p < P2_GRID; p += P2_BLOCK)
            acc += __ldcg(&g_partials[p]);
        sm[threadIdx.x] = acc;
        __syncthreads();
#pragma unroll
        for (int s = P2_BLOCK / 2; s > 0; s >>= 1) {
            if (threadIdx.x < s) sm[threadIdx.x] += sm[threadIdx.x + s];
            __syncthreads();
        }
        if (threadIdx.x == 0)
            out[0] = sm[0] * (1.0f / (float)NPIX);   // MULTIPLIER = 1.0
    }
}

extern "C" void kernel_launch(void* const* d_in, const int* in_sizes, int n_in,
                              void* d_out, int out_size) {
    const float* sig1    = (const float*)d_in[0];   // N f32
    const float* sig2    = (const float*)d_in[1];   // 3N f32
    const float* weights = (const float*)d_in[2];   // K*N f32
    const int*   nb      = (const int*)d_in[3];     // K*N int32
    float* out = (float*)d_out;

    pack_kernel<<<NPIX / 256, 256>>>(sig1, sig2);
    loss_kernel<<<P2_GRID, P2_BLOCK>>>(weights, nb, out);
}